// round 1
// baseline (speedup 1.0000x reference)
#include <cuda_runtime.h>
#include <math.h>

// Problem dims
#define Bsz 256
#define Ssz 128
#define Tsz 64
#define Isz 63
#define Hsz 1024
#define G3  (3*Hsz)   // 3072

// Scratch (device globals — no allocations allowed)
__device__ float g_GI[(size_t)Bsz * Ssz * G3];   // encoder gi_all (B*S, 3H)  ~403 MB
__device__ float g_G2[(size_t)Bsz * Tsz * G3];   // decoder gi     (B*T, 3H)  ~201 MB
__device__ float g_GH[(size_t)Bsz * G3];         // gh buffer      (B, 3H)
__device__ float g_states[(size_t)Bsz * Tsz * Hsz]; // decoder states (B*T, H)
__device__ float g_h[(size_t)Bsz * Hsz];         // recurrent hidden (B, H)

// -------------------------------------------------------------------------
// C[m][n] = bias[n] + sum_k A[m*lda + k] * W[n*K + k]
// Tiles: BM=BN=64, BK=16, 256 threads, 4x4 micro-tile per thread.
// M is always a multiple of 64 here; N and K are guarded.
// -------------------------------------------------------------------------
__global__ __launch_bounds__(256) void sgemm_bias(
    const float* __restrict__ A, int lda,
    const float* __restrict__ W,          // N x K row-major (ldw == K)
    const float* __restrict__ bias,
    float* __restrict__ C,                // M x N (ldc == N)
    int N, int K)
{
    __shared__ float As[16][64];
    __shared__ float Bs[16][64];

    const int tid  = threadIdx.x;
    const int tx   = tid & 15;       // n direction
    const int ty   = tid >> 4;       // m direction
    const int row0 = blockIdx.y << 6;
    const int col0 = blockIdx.x << 6;

    // loader indices: each thread loads 4 elems of A-tile and 4 of B-tile
    const int lm = tid >> 2;          // 0..63 (m for A, n for B)
    const int lk = (tid & 3) << 2;    // 0,4,8,12

    float acc[4][4] = {};

    for (int k0 = 0; k0 < K; k0 += 16) {
#pragma unroll
        for (int c = 0; c < 4; c++) {
            const int k = k0 + lk + c;
            As[lk + c][lm] = (k < K) ? A[(size_t)(row0 + lm) * lda + k] : 0.f;
            const int n = col0 + lm;
            Bs[lk + c][lm] = (k < K && n < N) ? W[(size_t)n * K + k] : 0.f;
        }
        __syncthreads();

#pragma unroll
        for (int k = 0; k < 16; k++) {
            const float4 av = *reinterpret_cast<const float4*>(&As[k][ty << 2]);
            const float4 bv = *reinterpret_cast<const float4*>(&Bs[k][tx << 2]);
            const float a[4] = {av.x, av.y, av.z, av.w};
            const float b[4] = {bv.x, bv.y, bv.z, bv.w};
#pragma unroll
            for (int i = 0; i < 4; i++)
#pragma unroll
                for (int j = 0; j < 4; j++)
                    acc[i][j] = fmaf(a[i], b[j], acc[i][j]);
        }
        __syncthreads();
    }

#pragma unroll
    for (int i = 0; i < 4; i++) {
        const int m = row0 + (ty << 2) + i;
#pragma unroll
        for (int j = 0; j < 4; j++) {
            const int n = col0 + (tx << 2) + j;
            if (n < N)
                C[(size_t)m * N + n] = acc[i][j] + bias[n];
        }
    }
}

// -------------------------------------------------------------------------
__global__ void zero_h_kernel()
{
    const int idx = blockIdx.x * blockDim.x + threadIdx.x;
    g_h[idx] = 0.f;
}

__device__ __forceinline__ float sigf(float x) { return 1.f / (1.f + expf(-x)); }

// Encoder gates: h = (1-z)*n + z*h, in place. idx over B*H.
__global__ void gates_enc_kernel(int t)
{
    const int idx = blockIdx.x * blockDim.x + threadIdx.x;
    const int b = idx >> 10;            // /H
    const int j = idx & (Hsz - 1);
    const float* gi = g_GI + ((size_t)b * Ssz + t) * G3;
    const float* gh = g_GH + (size_t)b * G3;

    const float r  = sigf(gi[j]          + gh[j]);
    const float z  = sigf(gi[Hsz + j]    + gh[Hsz + j]);
    const float nn = tanhf(gi[2*Hsz + j] + r * gh[2*Hsz + j]);
    const float hp = g_h[idx];
    g_h[idx] = (1.f - z) * nn + z * hp;
}

// Decoder gates: every timestep uses the same enc_h and the same gh row.
// idx over B*T*H.
__global__ void gates_dec_kernel()
{
    const size_t idx = (size_t)blockIdx.x * blockDim.x + threadIdx.x;
    const int j  = (int)(idx & (Hsz - 1));
    const int bt = (int)(idx >> 10);
    const int b  = bt >> 6;             // /T
    const float* gi = g_G2 + (size_t)bt * G3;
    const float* gh = g_GH + (size_t)b * G3;

    const float r  = sigf(gi[j]          + gh[j]);
    const float z  = sigf(gi[Hsz + j]    + gh[Hsz + j]);
    const float nn = tanhf(gi[2*Hsz + j] + r * gh[2*Hsz + j]);
    const float hp = g_h[(size_t)b * Hsz + j];
    g_states[idx] = (1.f - z) * nn + z * hp;
}

// -------------------------------------------------------------------------
extern "C" void kernel_launch(void* const* d_in, const int* in_sizes, int n_in,
                              void* d_out, int out_size)
{
    const float* enc_in  = (const float*)d_in[0];
    const float* dec_in  = (const float*)d_in[1];
    const float* enc_Wih = (const float*)d_in[2];
    const float* enc_Whh = (const float*)d_in[3];
    const float* enc_bih = (const float*)d_in[4];
    const float* enc_bhh = (const float*)d_in[5];
    const float* dec_Wih = (const float*)d_in[6];
    const float* dec_Whh = (const float*)d_in[7];
    const float* dec_bih = (const float*)d_in[8];
    const float* dec_bhh = (const float*)d_in[9];
    const float* proj_W  = (const float*)d_in[10];
    const float* proj_b  = (const float*)d_in[11];
    float* out = (float*)d_out;

    float *GI, *G2, *GH, *states, *h;
    cudaGetSymbolAddress((void**)&GI,     g_GI);
    cudaGetSymbolAddress((void**)&G2,     g_G2);
    cudaGetSymbolAddress((void**)&GH,     g_GH);
    cudaGetSymbolAddress((void**)&states, g_states);
    cudaGetSymbolAddress((void**)&h,      g_h);

    const dim3 blk(256);

    // h = 0
    zero_h_kernel<<<(Bsz * Hsz) / 256, blk>>>();

    // Encoder input gates for ALL timesteps in one GEMM:
    // GI (B*S, 3H) = enc_in (B*S, I) @ enc_Wih^T + enc_bih
    sgemm_bias<<<dim3(G3 / 64, (Bsz * Ssz) / 64), blk>>>(
        enc_in, Isz, enc_Wih, enc_bih, GI, G3, Isz);

    // Encoder recurrence: 128 sequential steps
    for (int t = 0; t < Ssz; t++) {
        // GH (B, 3H) = h (B, H) @ enc_Whh^T + enc_bhh
        sgemm_bias<<<dim3(G3 / 64, Bsz / 64), blk>>>(
            h, Hsz, enc_Whh, enc_bhh, GH, G3, Hsz);
        gates_enc_kernel<<<(Bsz * Hsz) / 256, blk>>>(t);
    }

    // Decoder hidden-side gates (shared by all T timesteps):
    // GH (B, 3H) = enc_h @ dec_Whh^T + dec_bhh
    sgemm_bias<<<dim3(G3 / 64, Bsz / 64), blk>>>(
        h, Hsz, dec_Whh, dec_bhh, GH, G3, Hsz);

    // Decoder input-side gates for all timesteps:
    // G2 (B*T, 3H) = dec_in (B*T, I) @ dec_Wih^T + dec_bih
    sgemm_bias<<<dim3(G3 / 64, (Bsz * Tsz) / 64), blk>>>(
        dec_in, Isz, dec_Wih, dec_bih, G2, G3, Isz);

    // Decoder gates -> states (B*T, H)
    gates_dec_kernel<<<(int)(((size_t)Bsz * Tsz * Hsz) / 256), blk>>>();

    // Projector: out (B*T, I) = states @ proj_W^T + proj_b
    sgemm_bias<<<dim3((Isz + 63) / 64, (Bsz * Tsz) / 64), blk>>>(
        states, Hsz, proj_W, proj_b, out, Isz, Hsz);
}

// round 2
// speedup vs baseline: 1.7779x; 1.7779x over previous
#include <cuda_runtime.h>
#include <math.h>

// Problem dims
#define Bsz 256
#define Ssz 128
#define Tsz 64
#define Isz 63
#define Hsz 1024
#define G3  (3*Hsz)   // 3072

// Scratch (device globals — no allocations allowed)
__device__ float g_GI[(size_t)Bsz * Ssz * G3];      // encoder gi_all (B*S, 3H)
__device__ float g_G2[(size_t)Bsz * Tsz * G3];      // decoder gi     (B*T, 3H)
__device__ float g_GH[(size_t)Bsz * G3];            // decoder gh     (B, 3H)
__device__ float g_states[(size_t)Bsz * Tsz * Hsz]; // decoder states (B*T, H)
__device__ float g_hbuf[2][(size_t)Bsz * Hsz];      // recurrent hidden, double buffered

// ---------------------------------------------------------------------------
// packed f32x2 helpers
// ---------------------------------------------------------------------------
typedef unsigned long long ull;

__device__ __forceinline__ ull dup2(float x) {
    ull r; asm("mov.b64 %0, {%1, %1};" : "=l"(r) : "f"(x)); return r;
}
__device__ __forceinline__ ull fma2(ull a, ull b, ull c) {
    ull d; asm("fma.rn.f32x2 %0, %1, %2, %3;" : "=l"(d) : "l"(a), "l"(b), "l"(c)); return d;
}
__device__ __forceinline__ void unpack2(ull v, float& lo, float& hi) {
    asm("mov.b64 {%0, %1}, %2;" : "=f"(lo), "=f"(hi) : "l"(v));
}

__device__ __forceinline__ float sigf(float x) { return 1.f / (1.f + expf(-x)); }

// ---------------------------------------------------------------------------
// Fused recurrence step: h_new = GRU(h_old, gi[:,t,:])
// Block tile: 64 batch rows x 32 hidden cols, all 3 gates (96 gh columns).
// Grid: (H/32=32, B/64=4) = 128 blocks, 128 threads each.
// Thread tile: 8 m x (2 j x 3 gates) -> 24 f32x2 accumulators (pair over j).
// ---------------------------------------------------------------------------
#define BK 16

__global__ __launch_bounds__(128) void gru_step_fused(
    const float* __restrict__ hin,    // (B, H)   = hbuf[t&1]
    float*       __restrict__ hout,   // (B, H)   = hbuf[(t+1)&1]
    const float* __restrict__ Whh,    // (3H, H)
    const float* __restrict__ bhh,    // (3H)
    int t)
{
    __shared__ float As[BK][64];   // [k][m]
    __shared__ float Bs[BK][96];   // [k][gate*32 + jj]

    const int tid = threadIdx.x;
    const int tn  = tid & 15;      // j-pair index: j local = tn*2, tn*2+1
    const int tm  = tid >> 4;      // m block: m local = tm*8 .. tm*8+7
    const int j0  = blockIdx.x << 5;   // 32 j per block
    const int b0  = blockIdx.y << 6;   // 64 batch per block

    ull acc[8][3];
#pragma unroll
    for (int i = 0; i < 8; i++)
#pragma unroll
        for (int g = 0; g < 3; g++) acc[i][g] = 0ull;

    // prefetch registers
    float4 pa[2], pb[3];

    // ---- global fetch of k-tile k0 into registers
    auto fetch = [&](int k0) {
#pragma unroll
        for (int i = 0; i < 2; i++) {
            const int c = tid + (i << 7);      // 0..255
            const int m = c >> 2;
            const int k = (c & 3) << 2;
            pa[i] = *reinterpret_cast<const float4*>(&hin[(size_t)(b0 + m) * Hsz + k0 + k]);
        }
#pragma unroll
        for (int i = 0; i < 3; i++) {
            const int c   = tid + (i << 7);    // 0..383
            const int row = c >> 2;            // 0..95
            const int k   = (c & 3) << 2;
            const int g   = row >> 5;
            const int jj  = row & 31;
            pb[i] = *reinterpret_cast<const float4*>(
                &Whh[(size_t)(g * Hsz + j0 + jj) * Hsz + k0 + k]);
        }
    };
    auto sts = [&]() {
#pragma unroll
        for (int i = 0; i < 2; i++) {
            const int c = tid + (i << 7);
            const int m = c >> 2;
            const int k = (c & 3) << 2;
            As[k + 0][m] = pa[i].x; As[k + 1][m] = pa[i].y;
            As[k + 2][m] = pa[i].z; As[k + 3][m] = pa[i].w;
        }
#pragma unroll
        for (int i = 0; i < 3; i++) {
            const int c   = tid + (i << 7);
            const int row = c >> 2;
            const int k   = (c & 3) << 2;
            Bs[k + 0][row] = pb[i].x; Bs[k + 1][row] = pb[i].y;
            Bs[k + 2][row] = pb[i].z; Bs[k + 3][row] = pb[i].w;
        }
    };

    fetch(0);
    sts();

    const int NT = Hsz / BK;   // 64 k-tiles
    for (int tt = 0; tt < NT; tt++) {
        __syncthreads();
        if (tt + 1 < NT) fetch((tt + 1) * BK);

#pragma unroll
        for (int k = 0; k < BK; k++) {
            // A: 8 consecutive m values
            const float4 a0 = *reinterpret_cast<const float4*>(&As[k][tm << 3]);
            const float4 a1 = *reinterpret_cast<const float4*>(&As[k][(tm << 3) + 4]);
            ull ad[8];
            ad[0] = dup2(a0.x); ad[1] = dup2(a0.y); ad[2] = dup2(a0.z); ad[3] = dup2(a0.w);
            ad[4] = dup2(a1.x); ad[5] = dup2(a1.y); ad[6] = dup2(a1.z); ad[7] = dup2(a1.w);
            // B: one j-pair per gate (native 8B loads)
            ull bp[3];
#pragma unroll
            for (int g = 0; g < 3; g++)
                bp[g] = *reinterpret_cast<const ull*>(&Bs[k][(g << 5) + (tn << 1)]);
#pragma unroll
            for (int i = 0; i < 8; i++)
#pragma unroll
                for (int g = 0; g < 3; g++)
                    acc[i][g] = fma2(ad[i], bp[g], acc[i][g]);
        }
        __syncthreads();
        if (tt + 1 < NT) sts();
    }

    // ---- epilogue: gh = acc + bhh, then GRU gates, write hout
    const int jA = j0 + (tn << 1);       // first j of the pair
    const float br0 = bhh[jA],            br1 = bhh[jA + 1];
    const float bz0 = bhh[Hsz + jA],      bz1 = bhh[Hsz + jA + 1];
    const float bn0 = bhh[2 * Hsz + jA],  bn1 = bhh[2 * Hsz + jA + 1];

#pragma unroll
    for (int i = 0; i < 8; i++) {
        const int m = b0 + (tm << 3) + i;                  // global batch row
        const float* gi = g_GI + ((size_t)m * Ssz + t) * G3;

        float ghr0, ghr1, ghz0, ghz1, ghn0, ghn1;
        unpack2(acc[i][0], ghr0, ghr1);
        unpack2(acc[i][1], ghz0, ghz1);
        unpack2(acc[i][2], ghn0, ghn1);
        ghr0 += br0; ghr1 += br1;
        ghz0 += bz0; ghz1 += bz1;
        ghn0 += bn0; ghn1 += bn1;

        const float2 gir = *reinterpret_cast<const float2*>(&gi[jA]);
        const float2 giz = *reinterpret_cast<const float2*>(&gi[Hsz + jA]);
        const float2 gin = *reinterpret_cast<const float2*>(&gi[2 * Hsz + jA]);
        const float2 hp  = *reinterpret_cast<const float2*>(&hin[(size_t)m * Hsz + jA]);

        const float r0 = sigf(gir.x + ghr0);
        const float r1 = sigf(gir.y + ghr1);
        const float z0 = sigf(giz.x + ghz0);
        const float z1 = sigf(giz.y + ghz1);
        const float n0 = tanhf(gin.x + r0 * ghn0);
        const float n1 = tanhf(gin.y + r1 * ghn1);

        float2 hn;
        hn.x = (1.f - z0) * n0 + z0 * hp.x;
        hn.y = (1.f - z1) * n1 + z1 * hp.y;
        *reinterpret_cast<float2*>(&hout[(size_t)m * Hsz + jA]) = hn;
    }
}

// ---------------------------------------------------------------------------
// Generic tiled SGEMM with bias (used for the parallel GEMMs)
// C[m][n] = bias[n] + sum_k A[m*lda+k] * W[n*K+k]
// ---------------------------------------------------------------------------
__global__ __launch_bounds__(256) void sgemm_bias(
    const float* __restrict__ A, int lda,
    const float* __restrict__ W,
    const float* __restrict__ bias,
    float* __restrict__ C,
    int N, int K)
{
    __shared__ float As[16][64];
    __shared__ float Bs[16][64];

    const int tid  = threadIdx.x;
    const int tx   = tid & 15;
    const int ty   = tid >> 4;
    const int row0 = blockIdx.y << 6;
    const int col0 = blockIdx.x << 6;

    const int lm = tid >> 2;
    const int lk = (tid & 3) << 2;

    float acc[4][4] = {};

    for (int k0 = 0; k0 < K; k0 += 16) {
#pragma unroll
        for (int c = 0; c < 4; c++) {
            const int k = k0 + lk + c;
            As[lk + c][lm] = (k < K) ? A[(size_t)(row0 + lm) * lda + k] : 0.f;
            const int n = col0 + lm;
            Bs[lk + c][lm] = (k < K && n < N) ? W[(size_t)n * K + k] : 0.f;
        }
        __syncthreads();

#pragma unroll
        for (int k = 0; k < 16; k++) {
            const float4 av = *reinterpret_cast<const float4*>(&As[k][ty << 2]);
            const float4 bv = *reinterpret_cast<const float4*>(&Bs[k][tx << 2]);
            const float a[4] = {av.x, av.y, av.z, av.w};
            const float b[4] = {bv.x, bv.y, bv.z, bv.w};
#pragma unroll
            for (int i = 0; i < 4; i++)
#pragma unroll
                for (int j = 0; j < 4; j++)
                    acc[i][j] = fmaf(a[i], b[j], acc[i][j]);
        }
        __syncthreads();
    }

#pragma unroll
    for (int i = 0; i < 4; i++) {
        const int m = row0 + (ty << 2) + i;
#pragma unroll
        for (int j = 0; j < 4; j++) {
            const int n = col0 + (tx << 2) + j;
            if (n < N)
                C[(size_t)m * N + n] = acc[i][j] + bias[n];
        }
    }
}

// ---------------------------------------------------------------------------
__global__ void zero_h_kernel()
{
    const int idx = blockIdx.x * blockDim.x + threadIdx.x;
    g_hbuf[0][idx] = 0.f;
}

// Decoder gates: every timestep uses the same enc_h and the same gh row.
__global__ void gates_dec_kernel(const float* __restrict__ hfin)
{
    const size_t idx = (size_t)blockIdx.x * blockDim.x + threadIdx.x;
    const int j  = (int)(idx & (Hsz - 1));
    const int bt = (int)(idx >> 10);
    const int b  = bt >> 6;
    const float* gi = g_G2 + (size_t)bt * G3;
    const float* gh = g_GH + (size_t)b * G3;

    const float r  = sigf(gi[j]          + gh[j]);
    const float z  = sigf(gi[Hsz + j]    + gh[Hsz + j]);
    const float nn = tanhf(gi[2*Hsz + j] + r * gh[2*Hsz + j]);
    const float hp = hfin[(size_t)b * Hsz + j];
    g_states[idx] = (1.f - z) * nn + z * hp;
}

// ---------------------------------------------------------------------------
extern "C" void kernel_launch(void* const* d_in, const int* in_sizes, int n_in,
                              void* d_out, int out_size)
{
    const float* enc_in  = (const float*)d_in[0];
    const float* dec_in  = (const float*)d_in[1];
    const float* enc_Wih = (const float*)d_in[2];
    const float* enc_Whh = (const float*)d_in[3];
    const float* enc_bih = (const float*)d_in[4];
    const float* enc_bhh = (const float*)d_in[5];
    const float* dec_Wih = (const float*)d_in[6];
    const float* dec_Whh = (const float*)d_in[7];
    const float* dec_bih = (const float*)d_in[8];
    const float* dec_bhh = (const float*)d_in[9];
    const float* proj_W  = (const float*)d_in[10];
    const float* proj_b  = (const float*)d_in[11];
    float* out = (float*)d_out;

    float *GI, *G2, *GH, *states, *hbuf;
    cudaGetSymbolAddress((void**)&GI,     g_GI);
    cudaGetSymbolAddress((void**)&G2,     g_G2);
    cudaGetSymbolAddress((void**)&GH,     g_GH);
    cudaGetSymbolAddress((void**)&states, g_states);
    cudaGetSymbolAddress((void**)&hbuf,   g_hbuf);
    float* h0 = hbuf;                                   // g_hbuf[0]
    float* h1 = hbuf + (size_t)Bsz * Hsz;               // g_hbuf[1]

    const dim3 blk256(256);

    // h(buf0) = 0
    zero_h_kernel<<<(Bsz * Hsz) / 256, blk256>>>();

    // Encoder input gates for ALL timesteps:
    // GI (B*S, 3H) = enc_in (B*S, I) @ enc_Wih^T + enc_bih
    sgemm_bias<<<dim3(G3 / 64, (Bsz * Ssz) / 64), blk256>>>(
        enc_in, Isz, enc_Wih, enc_bih, GI, G3, Isz);

    // Encoder recurrence: 128 sequential fused steps (GEMM + gates, 1 launch each)
    for (int t = 0; t < Ssz; t++) {
        const float* hin  = (t & 1) ? h1 : h0;
        float*       hout = (t & 1) ? h0 : h1;
        gru_step_fused<<<dim3(Hsz / 32, Bsz / 64), 128>>>(
            hin, hout, enc_Whh, enc_bhh, t);
    }
    // after 128 steps (even), final hidden is back in buf0
    float* enc_h = h0;

    // Decoder hidden-side gates (shared by all T timesteps)
    sgemm_bias<<<dim3(G3 / 64, Bsz / 64), blk256>>>(
        enc_h, Hsz, dec_Whh, dec_bhh, GH, G3, Hsz);

    // Decoder input-side gates for all timesteps
    sgemm_bias<<<dim3(G3 / 64, (Bsz * Tsz) / 64), blk256>>>(
        dec_in, Isz, dec_Wih, dec_bih, G2, G3, Isz);

    // Decoder gates -> states (B*T, H)
    gates_dec_kernel<<<(int)(((size_t)Bsz * Tsz * Hsz) / 256), blk256>>>(enc_h);

    // Projector: out (B*T, I) = states @ proj_W^T + proj_b
    sgemm_bias<<<dim3((Isz + 63) / 64, (Bsz * Tsz) / 64), blk256>>>(
        states, Hsz, proj_W, proj_b, out, Isz, Hsz);
}